// round 13
// baseline (speedup 1.0000x reference)
#include <cuda_runtime.h>
#include <cuda_fp16.h>
#include <math.h>
#include <stdint.h>

#define BSZ 4
#define DIM 64
#define HWN 65536          // 256*256

// ---------------- device scratch (static, allocation-free) ----------------
__device__ __align__(16) __half g_hA[BSZ * 192 * HWN];   // qkv fp16, [slice][x*256+y]
__device__ __align__(16) __half g_convh[BSZ * DIM * HWN];
__device__ __align__(16) __half g_outh[BSZ * DIM * HWN];
__device__ __align__(16) __half g_outv[BSZ * DIM * HWN];
__device__ float g_xsum[BSZ * DIM];
__device__ float g_cw  [BSZ];
__device__ float g_aw  [BSZ];
__device__ float g_sq  [2 * BSZ * DIM];

// ============================ helpers ============================
#define MMA16(d, a, b) \
    asm volatile("mma.sync.aligned.m16n8k16.row.col.f32.f16.f16.f32 " \
        "{%0,%1,%2,%3},{%4,%5,%6,%7},{%8,%9},{%0,%1,%2,%3};" \
        : "+f"((d)[0]), "+f"((d)[1]), "+f"((d)[2]), "+f"((d)[3]) \
        : "r"((a)[0]), "r"((a)[1]), "r"((a)[2]), "r"((a)[3]), \
          "r"((b)[0]), "r"((b)[1]))

#define LDSM4T(R0, R1, R2, R3, a) \
    asm volatile("ldmatrix.sync.aligned.m8n8.x4.trans.shared.b16 {%0,%1,%2,%3}, [%4];" \
        : "=r"(R0), "=r"(R1), "=r"(R2), "=r"(R3) : "r"(a))

#define CPA16(dst_u32, src_ptr) \
    asm volatile("cp.async.ca.shared.global [%0], [%1], 16;" \
        :: "r"(dst_u32), "l"(src_ptr) : "memory")
#define CP_COMMIT() asm volatile("cp.async.commit_group;" ::: "memory")
#define CP_WAIT(n)  asm volatile("cp.async.wait_group %0;" :: "n"(n) : "memory")

__device__ __forceinline__ uint32_t h2u(__half2 h) {
    return *reinterpret_cast<uint32_t*>(&h);
}
#define SWZ(r) (((r) + ((r) >> 3)) & 3)

// ---------------- 0) zero accumulators ----------------
__global__ void k_zero() {
    int t = threadIdx.x;
    if (t < 256) g_xsum[t] = 0.f;
    g_sq[t] = 0.f; g_sq[t + 256] = 0.f;
}

// ---------------- 1) gate MLP ----------------
__global__ void k_gate(const float* __restrict__ g1w, const float* __restrict__ g1b,
                       const float* __restrict__ g2w, const float* __restrict__ g2b) {
    int tid = threadIdx.x;
    int b = tid >> 4, j = tid & 15;
    __shared__ float sh1[4][16];
    float a = g1b[j];
    #pragma unroll
    for (int c = 0; c < 64; c++)
        a += (g_xsum[b * 64 + c] * (1.0f / HWN)) * g1w[j * 64 + c];
    sh1[b][j] = fmaxf(a, 0.f);
    __syncthreads();
    if (tid < 4) {
        float l0 = g2b[0], l1 = g2b[1];
        #pragma unroll
        for (int k = 0; k < 16; k++) {
            l0 += sh1[tid][k] * g2w[k];
            l1 += sh1[tid][k] * g2w[16 + k];
        }
        float m = fmaxf(l0, l1);
        float e0 = expf(l0 - m), e1 = expf(l1 - m);
        float inv = 1.f / (e0 + e1);
        g_cw[tid] = e0 * inv;
        g_aw[tid] = e1 * inv;
    }
}

// ---------------- 2) depthwise conv + channel-mean, 4 spatial tiles/block ----------------
__global__ void __launch_bounds__(256) k_conv_t(const float* __restrict__ x,
                       const float* __restrict__ w3, const float* __restrict__ b3,
                       const float* __restrict__ w5, const float* __restrict__ b5) {
    int bid = blockIdx.x;
    int bc = bid >> 4;
    int tbase = (bid & 15) * 4;
    int c = bc & 63;
    int tid = threadIdx.x;

    __shared__ float t[36 * 36];
    __shared__ float wc[25];
    __shared__ float sb[1];
    __shared__ float spart[8];
    if (tid < 25) {
        float w = w5[c * 25 + tid];
        int dh = tid / 5 - 2, dw = tid % 5 - 2;
        if (dh >= -1 && dh <= 1 && dw >= -1 && dw <= 1)
            w += w3[c * 9 + (dh + 1) * 3 + (dw + 1)];
        wc[tid] = w;
    }
    if (tid == 25) sb[0] = b3[c] + b5[c];

    const float* xp = x + (size_t)bc * HWN;
    int oh = tid >> 3, ow4 = (tid & 7) * 4;
    float xsum_t = 0.f;

    for (int tt = 0; tt < 4; tt++) {
        int tile = tbase + tt;
        int th = (tile >> 3) * 32, tw = (tile & 7) * 32;
        __syncthreads();
        for (int i = tid; i < 1296; i += 256) {
            int r = i / 36, col = i - r * 36;
            int gh = th - 2 + r, gw = tw - 2 + col;
            float v = 0.f;
            if ((unsigned)gh < 256u && (unsigned)gw < 256u) v = xp[gh * 256 + gw];
            t[i] = v;
        }
        __syncthreads();

        {
            const float* rp = t + (oh + 2) * 36 + ow4 + 2;
            xsum_t += rp[0] + rp[1] + rp[2] + rp[3];
        }
        float bias = sb[0];
        float a0 = bias, a1 = bias, a2 = bias, a3 = bias;
        #pragma unroll
        for (int dh = 0; dh < 5; dh++) {
            const float* row = t + (oh + dh) * 36 + ow4;
            float r0 = row[0], r1 = row[1], r2 = row[2], r3 = row[3];
            float r4 = row[4], r5 = row[5], r6 = row[6], r7 = row[7];
            const float* w = wc + dh * 5;
            float w0 = w[0], w1 = w[1], w2 = w[2], w3v = w[3], w4 = w[4];
            a0 += r0 * w0 + r1 * w1 + r2 * w2 + r3 * w3v + r4 * w4;
            a1 += r1 * w0 + r2 * w1 + r3 * w2 + r4 * w3v + r5 * w4;
            a2 += r2 * w0 + r3 * w1 + r4 * w2 + r5 * w3v + r6 * w4;
            a3 += r3 * w0 + r4 * w1 + r5 * w2 + r6 * w3v + r7 * w4;
        }
        uint2 u;
        u.x = h2u(__floats2half2_rn(a0, a1));
        u.y = h2u(__floats2half2_rn(a2, a3));
        *(uint2*)(g_convh + (size_t)bc * HWN + (th + oh) * 256 + tw + ow4) = u;
    }

    #pragma unroll
    for (int off = 16; off; off >>= 1) xsum_t += __shfl_xor_sync(0xFFFFFFFFu, xsum_t, off);
    if ((tid & 31) == 0) spart[tid >> 5] = xsum_t;
    __syncthreads();
    if (tid == 0) {
        float xs = 0.f;
        #pragma unroll
        for (int k = 0; k < 8; k++) xs += spart[k];
        atomicAdd(&g_xsum[bc], xs);
    }
}

// ---------------- 3) QKV projection: fp16 m16n8k16, 8 pixel-chunks/block ----------------
#define QH_ST 72
#define QKV16_DYN 96768

__global__ void __launch_bounds__(256, 2) k_qkv16(const float* __restrict__ x,
                                                  const float* __restrict__ wqkv) {
    extern __shared__ char qsm[];
    __half* As = (__half*)qsm;
    __half* Ws = (__half*)(qsm + 18432);
    float*  S  = (float*)(qsm + 46080);

    int tid = threadIdx.x;
    int wid = tid >> 5, lane = tid & 31;
    int gq = lane >> 2, tq = lane & 3;
    int wm = wid & 1, wn = wid >> 1;
    int mW = wm * 64, nW = wn * 48;

    int bid = blockIdx.x;
    int b = bid >> 6;
    int p0base = (bid & 63) << 10;
    const float* xb = x + (size_t)b * 64 * HWN;

    for (int i = tid; i < 192 * 16; i += 256) {
        int o = i >> 4, c4 = i & 15;
        float4 v = *(const float4*)(wqkv + o * 64 + c4 * 4);
        __half* d = Ws + o * QH_ST + c4 * 4;
        *(__half2*)d       = __floats2half2_rn(v.x, v.y);
        *(__half2*)(d + 2) = __floats2half2_rn(v.z, v.w);
    }

    for (int pc = 0; pc < 8; pc++) {
        int p0 = p0base + pc * 128;
        __syncthreads();
        for (int i = tid; i < 4096; i += 256) {
            int c2 = i >> 7, j = i & 127;
            float v0 = xb[(size_t)(2 * c2) * HWN + p0 + j];
            float v1 = xb[(size_t)(2 * c2 + 1) * HWN + p0 + j];
            *(__half2*)(As + j * QH_ST + 2 * (c2 ^ SWZ(j))) = __floats2half2_rn(v0, v1);
        }
        __syncthreads();

        float acc[4][6][4];
        #pragma unroll
        for (int mt = 0; mt < 4; mt++)
            #pragma unroll
            for (int nt = 0; nt < 6; nt++)
                #pragma unroll
                for (int j = 0; j < 4; j++) acc[mt][nt][j] = 0.f;

        #pragma unroll
        for (int ks = 0; ks < 4; ks++) {
            int kh = ks * 16;
            int cw0 = ks * 8 + tq;
            uint32_t bf[6][2];
            #pragma unroll
            for (int nt = 0; nt < 6; nt++) {
                const __half* bp = Ws + (nW + nt * 8 + gq) * QH_ST + kh + 2 * tq;
                bf[nt][0] = *(const uint32_t*)bp;
                bf[nt][1] = *(const uint32_t*)(bp + 8);
            }
            #pragma unroll
            for (int mt = 0; mt < 4; mt++) {
                int m = mW + mt * 16 + gq;
                int e0 = SWZ(m), e1 = SWZ(m + 8);
                const __half* r0 = As + m * QH_ST;
                const __half* r1 = As + (m + 8) * QH_ST;
                uint32_t af[4];
                af[0] = *(const uint32_t*)(r0 + 2 * (cw0 ^ e0));
                af[1] = *(const uint32_t*)(r1 + 2 * (cw0 ^ e1));
                af[2] = *(const uint32_t*)(r0 + 2 * ((cw0 + 4) ^ e0));
                af[3] = *(const uint32_t*)(r1 + 2 * ((cw0 + 4) ^ e1));
                #pragma unroll
                for (int nt = 0; nt < 6; nt++) MMA16(acc[mt][nt], af, bf[nt]);
            }
        }
        __syncthreads();

        __half* outb = g_hA + (size_t)b * 192 * HWN + p0;
        #pragma unroll
        for (int pass = 0; pass < 2; pass++) {
            if ((wn >> 1) == pass) {
                int ob = nW - pass * 96;
                #pragma unroll
                for (int mt = 0; mt < 4; mt++) {
                    int m = mW + mt * 16 + gq;
                    #pragma unroll
                    for (int nt = 0; nt < 6; nt++) {
                        int ol = ob + nt * 8 + 2 * tq;
                        S[ol * 132 + m]           = acc[mt][nt][0];
                        S[(ol + 1) * 132 + m]     = acc[mt][nt][1];
                        S[ol * 132 + m + 8]       = acc[mt][nt][2];
                        S[(ol + 1) * 132 + m + 8] = acc[mt][nt][3];
                    }
                }
            }
            __syncthreads();
            for (int i = tid; i < 96 * 32; i += 256) {
                int row = i >> 5, q = i & 31;
                float4 v = *(const float4*)(S + row * 132 + q * 4);
                int o = pass * 96 + row;
                uint2 u;
                u.x = h2u(__floats2half2_rn(v.x, v.y));
                u.y = h2u(__floats2half2_rn(v.z, v.w));
                *(uint2*)(outb + (size_t)o * HWN + q * 4) = u;
                if (o < 128) {
                    float sq = v.x * v.x + v.y * v.y + v.z * v.z + v.w * v.w;
                    #pragma unroll
                    for (int off = 16; off; off >>= 1) sq += __shfl_xor_sync(0xFFFFFFFFu, sq, off);
                    if ((tid & 31) == 0)
                        atomicAdd(&g_sq[o < 64 ? b * 64 + o : 256 + b * 64 + o - 64], sq);
                }
            }
            __syncthreads();
        }
    }
}

// ---------------- 4) fp16 mma attention: M=64 blocks, occupancy 2, k-chunk 32 ----------------
// halves: A 2x[64][40] @0 (2560 ea), B 2x[256][40] @5120 (10240 ea), Ps [64][296] @25600
#define H_AS(bi) ((bi) * 2560)
#define H_BS(bi) (5120 + (bi) * 10240)
#define H_PS 25600
#define AT_ST 72
#define BT_ST 264
#define ATTN16_DYN ((25600 + 64 * 296) * 2)   // 89088 bytes

__global__ void __launch_bounds__(256, 2) k_attn16(const float* __restrict__ scale) {
    extern __shared__ char dynsm[];
    __half* Hs = (__half*)dynsm;
    __half* Ps = Hs + H_PS;
    float*  Sf = (float*)dynsm;
    __shared__ float s_rows[256];
    __shared__ float s_inv[64];

    uint32_t smb = (uint32_t)__cvta_generic_to_shared(dynsm);

    int tid = threadIdx.x;
    int wid = tid >> 5, lane = tid & 31;
    int gq = lane >> 2, tq = lane & 3;
    int jj = lane & 7, lg = lane >> 3;
    int wm = wid & 1, wn = wid >> 1;
    int mW = wm * 32, nW = wn * 64;

    int bid = blockIdx.x;
    int qt = bid & 3;                  // quarter fastest -> L2 reuse of K/V
    int s = (bid >> 2) & 255;
    int dir = bid >> 10;
    int b = s >> 6, ch = s & 63, hd = ch & 7;
    int m0 = qt << 6;

    size_t sbase = ((size_t)b * 192 + ch) * HWN;
    const __half* Qp = g_hA + sbase;
    const __half* Kp = Qp + (size_t)64 * HWN;
    const __half* Vp = Qp + (size_t)128 * HWN;

    float nq = fmaxf(sqrtf(g_sq[s]), 1e-12f);
    float nk = fmaxf(sqrtf(g_sq[256 + s]), 1e-12f);
    float alpha = scale[hd] / (nq * nk);

    float acc[2][8][4];
    #pragma unroll
    for (int mt = 0; mt < 2; mt++)
        #pragma unroll
        for (int nt = 0; nt < 8; nt++)
            #pragma unroll
            for (int j = 0; j < 4; j++) acc[mt][nt][j] = 0.f;

    // ---- loaders (k-chunk 32) ----
    #define LOAD_A_DIR(bi, c0) do { \
        { int i = tid; if (i < 256) { \
            int r = i >> 2, q = i & 3; \
            CPA16(smb + (H_AS(bi) + r * 40 + q * 8) * 2, \
                  Qp + (size_t)(m0 + r) * 256 + (c0) + q * 8); } } } while (0)
    #define LOAD_A_TRN(bi, c0) do { \
        { int i = tid; if (i < 256) { \
            int r = i >> 3, q = i & 7; \
            CPA16(smb + (H_AS(bi) + r * AT_ST + q * 8) * 2, \
                  Qp + (size_t)((c0) + r) * 256 + m0 + q * 8); } } } while (0)
    #define LOAD_B_DIR(Bp, bi, c0) do { \
        for (int i = tid; i < 1024; i += 256) { \
            int r = i >> 2, q = i & 3; \
            CPA16(smb + (H_BS(bi) + r * 40 + q * 8) * 2, \
                  (Bp) + (size_t)r * 256 + (c0) + q * 8); \
        } } while (0)
    #define LOAD_B_TRN(Bp, bi, c0) do { \
        for (int i = tid; i < 1024; i += 256) { \
            int r = i >> 5, q = i & 31; \
            CPA16(smb + (H_BS(bi) + r * BT_ST + q * 8) * 2, \
                  (Bp) + (size_t)((c0) + r) * 256 + q * 8); \
        } } while (0)
    #define LOAD_G1(bi, c0) do { \
        if (dir == 0) { LOAD_A_DIR(bi, c0); LOAD_B_DIR(Kp, bi, c0); } \
        else          { LOAD_A_TRN(bi, c0); LOAD_B_TRN(Kp, bi, c0); } } while (0)

    int atrn_off = (jj + ((lg & 2) ? 8 : 0)) * AT_ST + (lg & 1) * 8;
    int btrn_off = (jj + ((lg & 1) ? 8 : 0)) * BT_ST + ((lg & 2) ? 8 : 0);

    LOAD_G1(0, 0);
    CP_COMMIT();

    // ======================= GEMM1 (8 chunks of k=32) =======================
    for (int cc = 0; cc < 8; cc++) {
        if (cc < 7) {
            LOAD_G1((cc + 1) & 1, (cc + 1) * 32);
            CP_COMMIT();
            CP_WAIT(1);
        } else {
            CP_WAIT(0);
        }
        __syncthreads();
        int cb = cc & 1;
        if (dir == 0) {
            const __half* Asb = Hs + H_AS(cb);
            const __half* Bsb = Hs + H_BS(cb);
            #pragma unroll
            for (int ks = 0; ks < 2; ks++) {
                int k0 = ks * 16;
                uint32_t bf[8][2];
                #pragma unroll
                for (int nt = 0; nt < 8; nt++) {
                    const __half* bp = Bsb + (nW + nt * 8 + gq) * 40 + k0 + 2 * tq;
                    bf[nt][0] = *(const uint32_t*)bp;
                    bf[nt][1] = *(const uint32_t*)(bp + 8);
                }
                #pragma unroll
                for (int mt = 0; mt < 2; mt++) {
                    const __half* ap = Asb + (mW + mt * 16 + gq) * 40 + k0 + 2 * tq;
                    uint32_t af[4];
                    af[0] = *(const uint32_t*)ap;
                    af[1] = *(const uint32_t*)(ap + 320);
                    af[2] = *(const uint32_t*)(ap + 8);
                    af[3] = *(const uint32_t*)(ap + 328);
                    #pragma unroll
                    for (int nt = 0; nt < 8; nt++) MMA16(acc[mt][nt], af, bf[nt]);
                }
            }
        } else {
            uint32_t abase = smb + (H_AS(cb) + atrn_off + mW) * 2;
            uint32_t bbase = smb + (H_BS(cb) + btrn_off + nW) * 2;
            #pragma unroll
            for (int ks = 0; ks < 2; ks++) {
                int k0 = ks * 16;
                uint32_t bf[8][2];
                #pragma unroll
                for (int p = 0; p < 4; p++) {
                    LDSM4T(bf[2 * p][0], bf[2 * p][1], bf[2 * p + 1][0], bf[2 * p + 1][1],
                           bbase + (k0 * BT_ST + p * 16) * 2);
                }
                #pragma unroll
                for (int mt = 0; mt < 2; mt++) {
                    uint32_t af[4];
                    LDSM4T(af[0], af[1], af[2], af[3],
                           abase + (k0 * AT_ST + mt * 16) * 2);
                    #pragma unroll
                    for (int nt = 0; nt < 8; nt++) MMA16(acc[mt][nt], af, bf[nt]);
                }
            }
        }
        __syncthreads();
    }

    // prologue for GEMM2: V chunks 0 and 1 under the softmax
    if (dir == 0) { LOAD_B_TRN(Vp, 0, 0); } else { LOAD_B_DIR(Vp, 0, 0); }
    CP_COMMIT();
    if (dir == 0) { LOAD_B_TRN(Vp, 1, 32); } else { LOAD_B_DIR(Vp, 1, 32); }
    CP_COMMIT();

    // ======================= softmax =======================
    #pragma unroll
    for (int mt = 0; mt < 2; mt++) {
        int r0 = mW + mt * 16 + gq;
        float rs0 = 0.f, rs1 = 0.f;
        #pragma unroll
        for (int nt = 0; nt < 8; nt++) {
            float e0 = __expf(fminf(acc[mt][nt][0] * alpha, 80.f));
            float e1 = __expf(fminf(acc[mt][nt][1] * alpha, 80.f));
            float e2 = __expf(fminf(acc[mt][nt][2] * alpha, 80.f));
            float e3 = __expf(fminf(acc[mt][nt][3] * alpha, 80.f));
            __half2 h01 = __floats2half2_rn(e0, e1);
            __half2 h23 = __floats2half2_rn(e2, e3);
            float2 f01 = __half22float2(h01);
            float2 f23 = __half22float2(h23);
            rs0 += f01.x + f01.y;
            rs1 += f23.x + f23.y;
            int c = nW + nt * 8 + 2 * tq;
            *(__half2*)(Ps + r0 * 296 + c)       = h01;
            *(__half2*)(Ps + (r0 + 8) * 296 + c) = h23;
        }
        rs0 += __shfl_xor_sync(0xFFFFFFFFu, rs0, 1);
        rs0 += __shfl_xor_sync(0xFFFFFFFFu, rs0, 2);
        rs1 += __shfl_xor_sync(0xFFFFFFFFu, rs1, 1);
        rs1 += __shfl_xor_sync(0xFFFFFFFFu, rs1, 2);
        if (tq == 0) {
            s_rows[wn * 64 + r0]     = rs0;
            s_rows[wn * 64 + r0 + 8] = rs1;
        }
    }
    __syncthreads();
    if (tid < 64)
        s_inv[tid] = 1.0f / (s_rows[tid] + s_rows[64 + tid] + s_rows[128 + tid] + s_rows[192 + tid]);

    #pragma unroll
    for (int mt = 0; mt < 2; mt++)
        #pragma unroll
        for (int nt = 0; nt < 8; nt++)
            #pragma unroll
            for (int j = 0; j < 4; j++) acc[mt][nt][j] = 0.f;

    // ======================= GEMM2 (8 chunks, prefetch depth 2) =======================
    for (int cc = 0; cc < 8; cc++) {
        if (cc < 7) CP_WAIT(1); else CP_WAIT(0);
        __syncthreads();
        int cb = cc & 1;
        const __half* Bsb = Hs + H_BS(cb);
        uint32_t bbase = smb + (H_BS(cb) + btrn_off + nW) * 2;
        #pragma unroll
        for (int ks = 0; ks < 2; ks++) {
            int k0 = ks * 16;
            int c0k = cc * 32 + k0;
            uint32_t bf[8][2];
            if (dir == 0) {
                #pragma unroll
                for (int p = 0; p < 4; p++) {
                    LDSM4T(bf[2 * p][0], bf[2 * p][1], bf[2 * p + 1][0], bf[2 * p + 1][1],
                           bbase + (k0 * BT_ST + p * 16) * 2);
                }
            } else {
                #pragma unroll
                for (int nt = 0; nt < 8; nt++) {
                    const __half* bp = Bsb + (nW + nt * 8 + gq) * 40 + k0 + 2 * tq;
                    bf[nt][0] = *(const uint32_t*)bp;
                    bf[nt][1] = *(const uint32_t*)(bp + 8);
                }
            }
            #pragma unroll
            for (int mt = 0; mt < 2; mt++) {
                const __half* ap = Ps + (mW + mt * 16 + gq) * 296 + c0k + 2 * tq;
                uint32_t af[4];
                af[0] = *(const uint32_t*)ap;
                af[1] = *(const uint32_t*)(ap + 2368);
                af[2] = *(const uint32_t*)(ap + 8);
                af[3] = *(const uint32_t*)(ap + 2376);
                #pragma unroll
                for (int nt = 0; nt < 8; nt++) MMA16(acc[mt][nt], af, bf[nt]);
            }
        }
        __syncthreads();
        if (cc < 6) {
            if (dir == 0) { LOAD_B_TRN(Vp, cc & 1, (cc + 2) * 32); }
            else          { LOAD_B_DIR(Vp, cc & 1, (cc + 2) * 32); }
            CP_COMMIT();
        }
    }

    // ======================= epilogue (single pass, fp16 out) =======================
    if (dir == 0) {
        // Sf [64][260] f32
        #pragma unroll
        for (int mt = 0; mt < 2; mt++) {
            int rg = mW + mt * 16 + gq;
            float i0 = s_inv[rg], i1 = s_inv[rg + 8];
            #pragma unroll
            for (int nt = 0; nt < 8; nt++) {
                int c = nW + nt * 8 + 2 * tq;
                *(float2*)(Sf + rg * 260 + c) =
                    make_float2(acc[mt][nt][0] * i0, acc[mt][nt][1] * i0);
                *(float2*)(Sf + (rg + 8) * 260 + c) =
                    make_float2(acc[mt][nt][2] * i1, acc[mt][nt][3] * i1);
            }
        }
        __syncthreads();
        __half* O = g_outh + (size_t)s * HWN;
        for (int i = tid; i < 4096; i += 256) {
            int r = i >> 6, q = i & 63;
            float4 u = *(const float4*)(Sf + r * 260 + q * 4);
            uint2 o;
            o.x = h2u(__floats2half2_rn(u.x, u.y));
            o.y = h2u(__floats2half2_rn(u.z, u.w));
            *(uint2*)(O + (size_t)(m0 + r) * 256 + q * 4) = o;
        }
    } else {
        // Sf [256][68] f32
        #pragma unroll
        for (int mt = 0; mt < 2; mt++) {
            int rg = mW + mt * 16 + gq;
            float i0 = s_inv[rg], i1 = s_inv[rg + 8];
            #pragma unroll
            for (int nt = 0; nt < 8; nt++) {
                int c = nW + nt * 8 + 2 * tq;
                Sf[c * 68 + rg]           = acc[mt][nt][0] * i0;
                Sf[(c + 1) * 68 + rg]     = acc[mt][nt][1] * i0;
                Sf[c * 68 + rg + 8]       = acc[mt][nt][2] * i1;
                Sf[(c + 1) * 68 + rg + 8] = acc[mt][nt][3] * i1;
            }
        }
        __syncthreads();
        __half* O = g_outv + (size_t)s * HWN;
        for (int i = tid; i < 4096; i += 256) {
            int n = i >> 4, q = i & 15;
            float4 u = *(const float4*)(Sf + n * 68 + q * 4);
            uint2 o;
            o.x = h2u(__floats2half2_rn(u.x, u.y));
            o.y = h2u(__floats2half2_rn(u.z, u.w));
            *(uint2*)(O + (size_t)n * 256 + m0 + q * 4) = o;
        }
    }
    #undef LOAD_A_DIR
    #undef LOAD_A_TRN
    #undef LOAD_B_DIR
    #undef LOAD_B_TRN
    #undef LOAD_G1
}

// ---------------- 5) gated fusion + projection: fp16 m16n8k16, 8 chunks/block ----------------
#define QF16_DYN 61440

__global__ void __launch_bounds__(256, 2) k_fuse16(const float* __restrict__ wp,
                                                   const float* __restrict__ bp,
                                                   float* __restrict__ out) {
    extern __shared__ char fsm[];
    __half* As = (__half*)fsm;
    __half* Ws = (__half*)(fsm + 18432);
    float*  S  = (float*)(fsm + 27648);

    int tid = threadIdx.x;
    int wid = tid >> 5, lane = tid & 31;
    int gq = lane >> 2, tq = lane & 3;
    int wm = wid & 1, wn = wid >> 1;
    int mW = wm * 64, nW = wn * 16;

    int bid = blockIdx.x;
    int b = bid >> 6;
    int p0base = (bid & 63) << 10;
    float cw = g_cw[b], aw = g_aw[b];

    for (int i = tid; i < 64 * 16; i += 256) {
        int o = i >> 4, c4 = i & 15;
        float4 v = *(const float4*)(wp + o * 64 + c4 * 4);
        __half* d = Ws + o * QH_ST + c4 * 4;
        *(__half2*)d       = __floats2half2_rn(v.x, v.y);
        *(__half2*)(d + 2) = __floats2half2_rn(v.z, v.w);
    }

    for (int pc = 0; pc < 8; pc++) {
        int p0 = p0base + pc * 128;
        __syncthreads();
        for (int i = tid; i < 4096; i += 256) {
            int c2 = i >> 7, j = i & 127;
            size_t off0 = ((size_t)(b * 64 + 2 * c2)) * HWN + p0 + j;
            size_t off1 = off0 + HWN;
            float v0 = cw * __half2float(g_convh[off0])
                     + aw * (__half2float(g_outh[off0]) + __half2float(g_outv[off0]));
            float v1 = cw * __half2float(g_convh[off1])
                     + aw * (__half2float(g_outh[off1]) + __half2float(g_outv[off1]));
            *(__half2*)(As + j * QH_ST + 2 * (c2 ^ SWZ(j))) = __floats2half2_rn(v0, v1);
        }
        __syncthreads();

        float acc[4][2][4];
        #pragma unroll
        for (int mt = 0; mt < 4; mt++)
            #pragma unroll
            for (int nt = 0; nt < 2; nt++)
                #pragma unroll
                for (int j = 0; j < 4; j++) acc[mt][nt][j] = 0.f;

        #pragma unroll
        for (int ks = 0; ks < 4; ks++) {
            int kh = ks * 16;
            int cw0 = ks * 8 + tq;
            uint32_t bf[2][2];
            #pragma unroll
            for (int nt = 0; nt < 2; nt++) {
                const __half* bpp = Ws + (nW + nt * 8 + gq) * QH_ST + kh + 2 * tq;
                bf[nt][0] = *(const uint32_t*)bpp;
                bf[nt][1] = *(const uint32_t*)(bpp + 8);
            }
            #pragma unroll
            for (int mt = 0; mt < 4; mt++) {
                int m = mW + mt * 16 + gq;
                int e0 = SWZ(m), e1 = SWZ(m + 8);
                const __half* r0 = As + m * QH_ST;
                const __half* r1 = As + (m + 8) * QH_ST;
                uint32_t af[4];
                af[0] = *(const uint32_t*)(r0 + 2 * (cw0 ^ e0));
                af[1] = *(const uint32_t*)(r1 + 2 * (cw0 ^ e1));
                af[2] = *(const uint32_t*)(r0 + 2 * ((cw0 + 4) ^ e0));
                af[3] = *(const uint32_t*)(r1 + 2 * ((cw0 + 4) ^ e1));
                #pragma unroll
                for (int nt = 0; nt < 2; nt++) MMA16(acc[mt][nt], af, bf[nt]);
            }
        }
        __syncthreads();

        #pragma unroll
        for (int mt = 0; mt < 4; mt++) {
            int m = mW + mt * 16 + gq;
            #pragma unroll
            for (int nt = 0; nt < 2; nt++) {
                int o = nW + nt * 8 + 2 * tq;
                S[o * 132 + m]           = acc[mt][nt][0];
                S[(o + 1) * 132 + m]     = acc[mt][nt][1];
                S[o * 132 + m + 8]       = acc[mt][nt][2];
                S[(o + 1) * 132 + m + 8] = acc[mt][nt][3];
            }
        }
        __syncthreads();
        for (int i = tid; i < 2048; i += 256) {
            int row = i >> 5, q = i & 31;
            float4 v = *(const float4*)(S + row * 132 + q * 4);
            float bb = __ldg(bp + row);
            v.x += bb; v.y += bb; v.z += bb; v.w += bb;
            *(float4*)(out + ((size_t)b * 64 + row) * HWN + p0 + q * 4) = v;
        }
    }
}

// ---------------- launcher ----------------
extern "C" void kernel_launch(void* const* d_in, const int* in_sizes, int n_in,
                              void* d_out, int out_size) {
    const float* x    = (const float*)d_in[0];
    const float* w3   = (const float*)d_in[1];
    const float* b3   = (const float*)d_in[2];
    const float* w5   = (const float*)d_in[3];
    const float* b5   = (const float*)d_in[4];
    const float* wqkv = (const float*)d_in[5];
    const float* scl  = (const float*)d_in[6];
    const float* g1w  = (const float*)d_in[7];
    const float* g1b  = (const float*)d_in[8];
    const float* g2w  = (const float*)d_in[9];
    const float* g2b  = (const float*)d_in[10];
    const float* wp   = (const float*)d_in[11];
    const float* bp   = (const float*)d_in[12];
    float* out = (float*)d_out;

    static bool configured = []() {
        cudaFuncSetAttribute(k_attn16, cudaFuncAttributeMaxDynamicSharedMemorySize, ATTN16_DYN);
        cudaFuncSetAttribute(k_qkv16, cudaFuncAttributeMaxDynamicSharedMemorySize, QKV16_DYN);
        cudaFuncSetAttribute(k_fuse16, cudaFuncAttributeMaxDynamicSharedMemorySize, QF16_DYN);
        return true;
    }();
    (void)configured;

    k_zero<<<1, 512>>>();
    k_conv_t<<<4096, 256>>>(x, w3, b3, w5, b5);
    k_qkv16<<<256, 256, QKV16_DYN>>>(x, wqkv);
    k_gate<<<1, 64>>>(g1w, g1b, g2w, g2b);
    k_attn16<<<2048, 256, ATTN16_DYN>>>(scl);
    k_fuse16<<<256, 256, QF16_DYN>>>(wp, bp, out);
}

// round 14
// speedup vs baseline: 1.0711x; 1.0711x over previous
#include <cuda_runtime.h>
#include <cuda_fp16.h>
#include <math.h>
#include <stdint.h>

#define BSZ 4
#define DIM 64
#define HWN 65536          // 256*256

// ---------------- device scratch (static, allocation-free) ----------------
__device__ __align__(16) __half g_hA[BSZ * 192 * HWN];   // qkv fp16, [slice][x*256+y]
__device__ __align__(16) __half g_convh[BSZ * DIM * HWN];
__device__ __align__(16) __half g_outh[BSZ * DIM * HWN];
__device__ __align__(16) __half g_outv[BSZ * DIM * HWN];
__device__ float g_xsum[BSZ * DIM];
__device__ float g_sq  [2 * BSZ * DIM];     // [0..255]=sum q^2, [256..511]=sum k^2

// ============================ helpers ============================
#define MMA16(d, a, b) \
    asm volatile("mma.sync.aligned.m16n8k16.row.col.f32.f16.f16.f32 " \
        "{%0,%1,%2,%3},{%4,%5,%6,%7},{%8,%9},{%0,%1,%2,%3};" \
        : "+f"((d)[0]), "+f"((d)[1]), "+f"((d)[2]), "+f"((d)[3]) \
        : "r"((a)[0]), "r"((a)[1]), "r"((a)[2]), "r"((a)[3]), \
          "r"((b)[0]), "r"((b)[1]))

#define LDSM4T(R0, R1, R2, R3, a) \
    asm volatile("ldmatrix.sync.aligned.m8n8.x4.trans.shared.b16 {%0,%1,%2,%3}, [%4];" \
        : "=r"(R0), "=r"(R1), "=r"(R2), "=r"(R3) : "r"(a))

#define CPA16(dst_u32, src_ptr) \
    asm volatile("cp.async.ca.shared.global [%0], [%1], 16;" \
        :: "r"(dst_u32), "l"(src_ptr) : "memory")
#define CP_COMMIT() asm volatile("cp.async.commit_group;" ::: "memory")
#define CP_WAIT(n)  asm volatile("cp.async.wait_group %0;" :: "n"(n) : "memory")

__device__ __forceinline__ uint32_t h2u(__half2 h) {
    return *reinterpret_cast<uint32_t*>(&h);
}
#define SWZ(r) (((r) + ((r) >> 3)) & 3)

// ---------------- 0) zero accumulators ----------------
__global__ void k_zero() {
    int t = threadIdx.x;
    if (t < 256) g_xsum[t] = 0.f;
    g_sq[t] = 0.f; g_sq[t + 256] = 0.f;
}

// ---------------- 1) depthwise conv + channel-mean, 4 spatial tiles/block ----------------
__global__ void __launch_bounds__(256) k_conv_t(const float* __restrict__ x,
                       const float* __restrict__ w3, const float* __restrict__ b3,
                       const float* __restrict__ w5, const float* __restrict__ b5) {
    int bid = blockIdx.x;
    int bc = bid >> 4;
    int tbase = (bid & 15) * 4;
    int c = bc & 63;
    int tid = threadIdx.x;

    __shared__ float t[36 * 36];
    __shared__ float wc[25];
    __shared__ float sb[1];
    __shared__ float spart[8];
    if (tid < 25) {
        float w = w5[c * 25 + tid];
        int dh = tid / 5 - 2, dw = tid % 5 - 2;
        if (dh >= -1 && dh <= 1 && dw >= -1 && dw <= 1)
            w += w3[c * 9 + (dh + 1) * 3 + (dw + 1)];
        wc[tid] = w;
    }
    if (tid == 25) sb[0] = b3[c] + b5[c];

    const float* xp = x + (size_t)bc * HWN;
    int oh = tid >> 3, ow4 = (tid & 7) * 4;
    float xsum_t = 0.f;

    for (int tt = 0; tt < 4; tt++) {
        int tile = tbase + tt;
        int th = (tile >> 3) * 32, tw = (tile & 7) * 32;
        __syncthreads();
        for (int i = tid; i < 1296; i += 256) {
            int r = i / 36, col = i - r * 36;
            int gh = th - 2 + r, gw = tw - 2 + col;
            float v = 0.f;
            if ((unsigned)gh < 256u && (unsigned)gw < 256u) v = xp[gh * 256 + gw];
            t[i] = v;
        }
        __syncthreads();

        {
            const float* rp = t + (oh + 2) * 36 + ow4 + 2;
            xsum_t += rp[0] + rp[1] + rp[2] + rp[3];
        }
        float bias = sb[0];
        float a0 = bias, a1 = bias, a2 = bias, a3 = bias;
        #pragma unroll
        for (int dh = 0; dh < 5; dh++) {
            const float* row = t + (oh + dh) * 36 + ow4;
            float r0 = row[0], r1 = row[1], r2 = row[2], r3 = row[3];
            float r4 = row[4], r5 = row[5], r6 = row[6], r7 = row[7];
            const float* w = wc + dh * 5;
            float w0 = w[0], w1 = w[1], w2 = w[2], w3v = w[3], w4 = w[4];
            a0 += r0 * w0 + r1 * w1 + r2 * w2 + r3 * w3v + r4 * w4;
            a1 += r1 * w0 + r2 * w1 + r3 * w2 + r4 * w3v + r5 * w4;
            a2 += r2 * w0 + r3 * w1 + r4 * w2 + r5 * w3v + r6 * w4;
            a3 += r3 * w0 + r4 * w1 + r5 * w2 + r6 * w3v + r7 * w4;
        }
        uint2 u;
        u.x = h2u(__floats2half2_rn(a0, a1));
        u.y = h2u(__floats2half2_rn(a2, a3));
        *(uint2*)(g_convh + (size_t)bc * HWN + (th + oh) * 256 + tw + ow4) = u;
    }

    #pragma unroll
    for (int off = 16; off; off >>= 1) xsum_t += __shfl_xor_sync(0xFFFFFFFFu, xsum_t, off);
    if ((tid & 31) == 0) spart[tid >> 5] = xsum_t;
    __syncthreads();
    if (tid == 0) {
        float xs = 0.f;
        #pragma unroll
        for (int k = 0; k < 8; k++) xs += spart[k];
        atomicAdd(&g_xsum[bc], xs);
    }
}

// ---------------- 2) QKV projection: fp16 m16n8k16, 8 pixel-chunks/block ----------------
#define QH_ST 72
#define QKV16_DYN 96768

__global__ void __launch_bounds__(256, 2) k_qkv16(const float* __restrict__ x,
                                                  const float* __restrict__ wqkv) {
    extern __shared__ char qsm[];
    __half* As = (__half*)qsm;
    __half* Ws = (__half*)(qsm + 18432);
    float*  S  = (float*)(qsm + 46080);

    int tid = threadIdx.x;
    int wid = tid >> 5, lane = tid & 31;
    int gq = lane >> 2, tq = lane & 3;
    int wm = wid & 1, wn = wid >> 1;
    int mW = wm * 64, nW = wn * 48;

    int bid = blockIdx.x;
    int b = bid >> 6;
    int p0base = (bid & 63) << 10;
    const float* xb = x + (size_t)b * 64 * HWN;

    for (int i = tid; i < 192 * 16; i += 256) {
        int o = i >> 4, c4 = i & 15;
        float4 v = *(const float4*)(wqkv + o * 64 + c4 * 4);
        __half* d = Ws + o * QH_ST + c4 * 4;
        *(__half2*)d       = __floats2half2_rn(v.x, v.y);
        *(__half2*)(d + 2) = __floats2half2_rn(v.z, v.w);
    }

    for (int pc = 0; pc < 8; pc++) {
        int p0 = p0base + pc * 128;
        __syncthreads();
        for (int i = tid; i < 4096; i += 256) {
            int c2 = i >> 7, j = i & 127;
            float v0 = xb[(size_t)(2 * c2) * HWN + p0 + j];
            float v1 = xb[(size_t)(2 * c2 + 1) * HWN + p0 + j];
            *(__half2*)(As + j * QH_ST + 2 * (c2 ^ SWZ(j))) = __floats2half2_rn(v0, v1);
        }
        __syncthreads();

        float acc[4][6][4];
        #pragma unroll
        for (int mt = 0; mt < 4; mt++)
            #pragma unroll
            for (int nt = 0; nt < 6; nt++)
                #pragma unroll
                for (int j = 0; j < 4; j++) acc[mt][nt][j] = 0.f;

        #pragma unroll
        for (int ks = 0; ks < 4; ks++) {
            int kh = ks * 16;
            int cw0 = ks * 8 + tq;
            uint32_t bf[6][2];
            #pragma unroll
            for (int nt = 0; nt < 6; nt++) {
                const __half* bp = Ws + (nW + nt * 8 + gq) * QH_ST + kh + 2 * tq;
                bf[nt][0] = *(const uint32_t*)bp;
                bf[nt][1] = *(const uint32_t*)(bp + 8);
            }
            #pragma unroll
            for (int mt = 0; mt < 4; mt++) {
                int m = mW + mt * 16 + gq;
                int e0 = SWZ(m), e1 = SWZ(m + 8);
                const __half* r0 = As + m * QH_ST;
                const __half* r1 = As + (m + 8) * QH_ST;
                uint32_t af[4];
                af[0] = *(const uint32_t*)(r0 + 2 * (cw0 ^ e0));
                af[1] = *(const uint32_t*)(r1 + 2 * (cw0 ^ e1));
                af[2] = *(const uint32_t*)(r0 + 2 * ((cw0 + 4) ^ e0));
                af[3] = *(const uint32_t*)(r1 + 2 * ((cw0 + 4) ^ e1));
                #pragma unroll
                for (int nt = 0; nt < 6; nt++) MMA16(acc[mt][nt], af, bf[nt]);
            }
        }
        __syncthreads();

        __half* outb = g_hA + (size_t)b * 192 * HWN + p0;
        #pragma unroll
        for (int pass = 0; pass < 2; pass++) {
            if ((wn >> 1) == pass) {
                int ob = nW - pass * 96;
                #pragma unroll
                for (int mt = 0; mt < 4; mt++) {
                    int m = mW + mt * 16 + gq;
                    #pragma unroll
                    for (int nt = 0; nt < 6; nt++) {
                        int ol = ob + nt * 8 + 2 * tq;
                        S[ol * 132 + m]           = acc[mt][nt][0];
                        S[(ol + 1) * 132 + m]     = acc[mt][nt][1];
                        S[ol * 132 + m + 8]       = acc[mt][nt][2];
                        S[(ol + 1) * 132 + m + 8] = acc[mt][nt][3];
                    }
                }
            }
            __syncthreads();
            for (int i = tid; i < 96 * 32; i += 256) {
                int row = i >> 5, q = i & 31;
                float4 v = *(const float4*)(S + row * 132 + q * 4);
                int o = pass * 96 + row;
                uint2 u;
                u.x = h2u(__floats2half2_rn(v.x, v.y));
                u.y = h2u(__floats2half2_rn(v.z, v.w));
                *(uint2*)(outb + (size_t)o * HWN + q * 4) = u;
                if (o < 128) {
                    float sq = v.x * v.x + v.y * v.y + v.z * v.z + v.w * v.w;
                    #pragma unroll
                    for (int off = 16; off; off >>= 1) sq += __shfl_xor_sync(0xFFFFFFFFu, sq, off);
                    if ((tid & 31) == 0)
                        atomicAdd(&g_sq[o < 64 ? b * 64 + o : 256 + b * 64 + o - 64], sq);
                }
            }
            __syncthreads();
        }
    }
}

// ---------------- 3) fp16 mma attention, transpose-free (round-12 config) ----------------
#define H_AS(bi) ((bi) * 9216)
#define H_BS(bi) (18432 + (bi) * 18432)
#define H_PS 55296
#define AT_ST 136
#define BT_ST 264
#define ATTN16_DYN ((55296 + 128 * 296) * 2)   // 186368 bytes

__global__ void __launch_bounds__(256, 1) k_attn16(const float* __restrict__ scale) {
    extern __shared__ char dynsm[];
    __half* Hs = (__half*)dynsm;
    __half* Ps = Hs + H_PS;
    float*  Sf = (float*)dynsm;
    __shared__ float s_rows[512];
    __shared__ float s_inv[128];

    uint32_t smb = (uint32_t)__cvta_generic_to_shared(dynsm);

    int tid = threadIdx.x;
    int wid = tid >> 5, lane = tid & 31;
    int gq = lane >> 2, tq = lane & 3;
    int jj = lane & 7, lg = lane >> 3;
    int wm = wid & 1, wn = wid >> 1;
    int mW = wm * 64, nW = wn * 64;

    int bid = blockIdx.x;
    int s = bid & 255, half = (bid >> 8) & 1, dir = bid >> 9;
    int b = s >> 6, ch = s & 63, hd = ch & 7;
    int m0 = half << 7;

    size_t sbase = ((size_t)b * 192 + ch) * HWN;
    const __half* Qp = g_hA + sbase;
    const __half* Kp = Qp + (size_t)64 * HWN;
    const __half* Vp = Qp + (size_t)128 * HWN;

    float nq = fmaxf(sqrtf(g_sq[s]), 1e-12f);
    float nk = fmaxf(sqrtf(g_sq[256 + s]), 1e-12f);
    float alpha = scale[hd] / (nq * nk);

    float acc[4][8][4];
    #pragma unroll
    for (int mt = 0; mt < 4; mt++)
        #pragma unroll
        for (int nt = 0; nt < 8; nt++)
            #pragma unroll
            for (int j = 0; j < 4; j++) acc[mt][nt][j] = 0.f;

    #define LOAD_A_DIR(bi, c0) do { \
        for (int i = tid; i < 1024; i += 256) { \
            int r = i >> 3, q = i & 7; \
            CPA16(smb + (H_AS(bi) + r * QH_ST + q * 8) * 2, \
                  Qp + (size_t)(m0 + r) * 256 + (c0) + q * 8); \
        } } while (0)
    #define LOAD_A_TRN(bi, c0) do { \
        for (int i = tid; i < 1024; i += 256) { \
            int r = i >> 4, q = i & 15; \
            CPA16(smb + (H_AS(bi) + r * AT_ST + q * 8) * 2, \
                  Qp + (size_t)((c0) + r) * 256 + m0 + q * 8); \
        } } while (0)
    #define LOAD_B_DIR(Bp, bi, c0) do { \
        for (int i = tid; i < 2048; i += 256) { \
            int r = i >> 3, q = i & 7; \
            CPA16(smb + (H_BS(bi) + r * QH_ST + q * 8) * 2, \
                  (Bp) + (size_t)r * 256 + (c0) + q * 8); \
        } } while (0)
    #define LOAD_B_TRN(Bp, bi, c0) do { \
        for (int i = tid; i < 2048; i += 256) { \
            int r = i >> 5, q = i & 31; \
            CPA16(smb + (H_BS(bi) + r * BT_ST + q * 8) * 2, \
                  (Bp) + (size_t)((c0) + r) * 256 + q * 8); \
        } } while (0)
    #define LOAD_G1(bi, c0) do { \
        if (dir == 0) { LOAD_A_DIR(bi, c0); LOAD_B_DIR(Kp, bi, c0); } \
        else          { LOAD_A_TRN(bi, c0); LOAD_B_TRN(Kp, bi, c0); } } while (0)

    int atrn_off = (jj + ((lg & 2) ? 8 : 0)) * AT_ST + (lg & 1) * 8;
    int btrn_off = (jj + ((lg & 1) ? 8 : 0)) * BT_ST + ((lg & 2) ? 8 : 0);

    LOAD_G1(0, 0);
    CP_COMMIT();

    // ======================= GEMM1 =======================
    for (int cc = 0; cc < 4; cc++) {
        if (cc < 3) {
            LOAD_G1((cc + 1) & 1, (cc + 1) * 64);
            CP_COMMIT();
            CP_WAIT(1);
        } else {
            CP_WAIT(0);
        }
        __syncthreads();
        int cb = cc & 1;
        if (dir == 0) {
            const __half* Asb = Hs + H_AS(cb);
            const __half* Bsb = Hs + H_BS(cb);
            #pragma unroll
            for (int ks = 0; ks < 4; ks++) {
                int k0 = ks * 16;
                uint32_t bf[8][2];
                #pragma unroll
                for (int nt = 0; nt < 8; nt++) {
                    const __half* bp = Bsb + (nW + nt * 8 + gq) * QH_ST + k0 + 2 * tq;
                    bf[nt][0] = *(const uint32_t*)bp;
                    bf[nt][1] = *(const uint32_t*)(bp + 8);
                }
                #pragma unroll
                for (int mt = 0; mt < 4; mt++) {
                    const __half* ap = Asb + (mW + mt * 16 + gq) * QH_ST + k0 + 2 * tq;
                    uint32_t af[4];
                    af[0] = *(const uint32_t*)ap;
                    af[1] = *(const uint32_t*)(ap + 8 * QH_ST);
                    af[2] = *(const uint32_t*)(ap + 8);
                    af[3] = *(const uint32_t*)(ap + 8 * QH_ST + 8);
                    #pragma unroll
                    for (int nt = 0; nt < 8; nt++) MMA16(acc[mt][nt], af, bf[nt]);
                }
            }
        } else {
            uint32_t abase = smb + (H_AS(cb) + atrn_off + mW) * 2;
            uint32_t bbase = smb + (H_BS(cb) + btrn_off + nW) * 2;
            #pragma unroll
            for (int ks = 0; ks < 4; ks++) {
                int k0 = ks * 16;
                uint32_t bf[8][2];
                #pragma unroll
                for (int p = 0; p < 4; p++) {
                    LDSM4T(bf[2 * p][0], bf[2 * p][1], bf[2 * p + 1][0], bf[2 * p + 1][1],
                           bbase + (k0 * BT_ST + p * 16) * 2);
                }
                #pragma unroll
                for (int mt = 0; mt < 4; mt++) {
                    uint32_t af[4];
                    LDSM4T(af[0], af[1], af[2], af[3],
                           abase + (k0 * AT_ST + mt * 16) * 2);
                    #pragma unroll
                    for (int nt = 0; nt < 8; nt++) MMA16(acc[mt][nt], af, bf[nt]);
                }
            }
        }
        __syncthreads();
    }

    if (dir == 0) { LOAD_B_TRN(Vp, 0, 0); } else { LOAD_B_DIR(Vp, 0, 0); }
    CP_COMMIT();
    if (dir == 0) { LOAD_B_TRN(Vp, 1, 64); } else { LOAD_B_DIR(Vp, 1, 64); }
    CP_COMMIT();

    // ======================= softmax =======================
    #pragma unroll
    for (int mt = 0; mt < 4; mt++) {
        int r0 = mW + mt * 16 + gq;
        float rs0 = 0.f, rs1 = 0.f;
        #pragma unroll
        for (int nt = 0; nt < 8; nt++) {
            float e0 = __expf(fminf(acc[mt][nt][0] * alpha, 80.f));
            float e1 = __expf(fminf(acc[mt][nt][1] * alpha, 80.f));
            float e2 = __expf(fminf(acc[mt][nt][2] * alpha, 80.f));
            float e3 = __expf(fminf(acc[mt][nt][3] * alpha, 80.f));
            __half2 h01 = __floats2half2_rn(e0, e1);
            __half2 h23 = __floats2half2_rn(e2, e3);
            float2 f01 = __half22float2(h01);
            float2 f23 = __half22float2(h23);
            rs0 += f01.x + f01.y;
            rs1 += f23.x + f23.y;
            int c = nW + nt * 8 + 2 * tq;
            *(__half2*)(Ps + r0 * 296 + c)       = h01;
            *(__half2*)(Ps + (r0 + 8) * 296 + c) = h23;
        }
        rs0 += __shfl_xor_sync(0xFFFFFFFFu, rs0, 1);
        rs0 += __shfl_xor_sync(0xFFFFFFFFu, rs0, 2);
        rs1 += __shfl_xor_sync(0xFFFFFFFFu, rs1, 1);
        rs1 += __shfl_xor_sync(0xFFFFFFFFu, rs1, 2);
        if (tq == 0) {
            s_rows[wn * 128 + r0]     = rs0;
            s_rows[wn * 128 + r0 + 8] = rs1;
        }
    }
    __syncthreads();
    if (tid < 128)
        s_inv[tid] = 1.0f / (s_rows[tid] + s_rows[128 + tid] + s_rows[256 + tid] + s_rows[384 + tid]);

    #pragma unroll
    for (int mt = 0; mt < 4; mt++)
        #pragma unroll
        for (int nt = 0; nt < 8; nt++)
            #pragma unroll
            for (int j = 0; j < 4; j++) acc[mt][nt][j] = 0.f;

    // ======================= GEMM2 (prefetch depth 2) =======================
    for (int cc = 0; cc < 4; cc++) {
        if (cc < 3) CP_WAIT(1); else CP_WAIT(0);
        __syncthreads();
        int cb = cc & 1;
        const __half* Bsb = Hs + H_BS(cb);
        uint32_t bbase = smb + (H_BS(cb) + btrn_off + nW) * 2;
        #pragma unroll
        for (int ks = 0; ks < 4; ks++) {
            int k0 = ks * 16;
            int c0k = cc * 64 + k0;
            uint32_t bf[8][2];
            if (dir == 0) {
                #pragma unroll
                for (int p = 0; p < 4; p++) {
                    LDSM4T(bf[2 * p][0], bf[2 * p][1], bf[2 * p + 1][0], bf[2 * p + 1][1],
                           bbase + (k0 * BT_ST + p * 16) * 2);
                }
            } else {
                #pragma unroll
                for (int nt = 0; nt < 8; nt++) {
                    const __half* bp = Bsb + (nW + nt * 8 + gq) * QH_ST + k0 + 2 * tq;
                    bf[nt][0] = *(const uint32_t*)bp;
                    bf[nt][1] = *(const uint32_t*)(bp + 8);
                }
            }
            #pragma unroll
            for (int mt = 0; mt < 4; mt++) {
                const __half* ap = Ps + (mW + mt * 16 + gq) * 296 + c0k + 2 * tq;
                uint32_t af[4];
                af[0] = *(const uint32_t*)ap;
                af[1] = *(const uint32_t*)(ap + 2368);
                af[2] = *(const uint32_t*)(ap + 8);
                af[3] = *(const uint32_t*)(ap + 2376);
                #pragma unroll
                for (int nt = 0; nt < 8; nt++) MMA16(acc[mt][nt], af, bf[nt]);
            }
        }
        __syncthreads();
        if (cc < 2) {
            if (dir == 0) { LOAD_B_TRN(Vp, cc & 1, (cc + 2) * 64); }
            else          { LOAD_B_DIR(Vp, cc & 1, (cc + 2) * 64); }
            CP_COMMIT();
        }
    }

    // ======================= epilogue: single-pass staging =======================
    if (dir == 0) {
        #pragma unroll
        for (int mt = 0; mt < 4; mt++) {
            int rg = mW + mt * 16 + gq;
            float i0 = s_inv[rg], i1 = s_inv[rg + 8];
            #pragma unroll
            for (int nt = 0; nt < 8; nt++) {
                int c = nW + nt * 8 + 2 * tq;
                *(float2*)(Sf + rg * 260 + c) =
                    make_float2(acc[mt][nt][0] * i0, acc[mt][nt][1] * i0);
                *(float2*)(Sf + (rg + 8) * 260 + c) =
                    make_float2(acc[mt][nt][2] * i1, acc[mt][nt][3] * i1);
            }
        }
        __syncthreads();
        __half* O = g_outh + (size_t)s * HWN;
        for (int i = tid; i < 8192; i += 256) {
            int r = i >> 6, q = i & 63;
            float4 u = *(const float4*)(Sf + r * 260 + q * 4);
            uint2 o;
            o.x = h2u(__floats2half2_rn(u.x, u.y));
            o.y = h2u(__floats2half2_rn(u.z, u.w));
            *(uint2*)(O + (size_t)(m0 + r) * 256 + q * 4) = o;
        }
    } else {
        #pragma unroll
        for (int mt = 0; mt < 4; mt++) {
            int rg = mW + mt * 16 + gq;
            float i0 = s_inv[rg], i1 = s_inv[rg + 8];
            #pragma unroll
            for (int nt = 0; nt < 8; nt++) {
                int c = nW + nt * 8 + 2 * tq;
                Sf[c * 132 + rg]           = acc[mt][nt][0] * i0;
                Sf[(c + 1) * 132 + rg]     = acc[mt][nt][1] * i0;
                Sf[c * 132 + rg + 8]       = acc[mt][nt][2] * i1;
                Sf[(c + 1) * 132 + rg + 8] = acc[mt][nt][3] * i1;
            }
        }
        __syncthreads();
        __half* O = g_outv + (size_t)s * HWN;
        for (int i = tid; i < 8192; i += 256) {
            int n = i >> 5, q = i & 31;
            float4 u = *(const float4*)(Sf + n * 132 + q * 4);
            uint2 o;
            o.x = h2u(__floats2half2_rn(u.x, u.y));
            o.y = h2u(__floats2half2_rn(u.z, u.w));
            *(uint2*)(O + (size_t)n * 256 + m0 + q * 4) = o;
        }
    }
    #undef LOAD_A_DIR
    #undef LOAD_A_TRN
    #undef LOAD_B_DIR
    #undef LOAD_B_TRN
    #undef LOAD_G1
}

// ---------------- 4) gated fusion + projection (gate MLP fused in) ----------------
#define QF16_DYN 61440

__global__ void __launch_bounds__(256, 2) k_fuse16(const float* __restrict__ wp,
                                                   const float* __restrict__ bp,
                                                   const float* __restrict__ g1w,
                                                   const float* __restrict__ g1b,
                                                   const float* __restrict__ g2w,
                                                   const float* __restrict__ g2b,
                                                   float* __restrict__ out) {
    extern __shared__ char fsm[];
    __half* As = (__half*)fsm;
    __half* Ws = (__half*)(fsm + 18432);
    float*  S  = (float*)(fsm + 27648);
    __shared__ float sh1[16];
    __shared__ float s_gate[2];

    int tid = threadIdx.x;
    int wid = tid >> 5, lane = tid & 31;
    int gq = lane >> 2, tq = lane & 3;
    int wm = wid & 1, wn = wid >> 1;
    int mW = wm * 64, nW = wn * 16;

    int bid = blockIdx.x;
    int b = bid >> 6;
    int p0base = (bid & 63) << 10;

    // ---- gate MLP computed in-block (hidden under the W tile load) ----
    if (tid < 16) {
        float a = g1b[tid];
        #pragma unroll
        for (int c = 0; c < 64; c++)
            a += (g_xsum[b * 64 + c] * (1.0f / HWN)) * g1w[tid * 64 + c];
        sh1[tid] = fmaxf(a, 0.f);
    }
    for (int i = tid; i < 64 * 16; i += 256) {
        int o = i >> 4, c4 = i & 15;
        float4 v = *(const float4*)(wp + o * 64 + c4 * 4);
        __half* d = Ws + o * QH_ST + c4 * 4;
        *(__half2*)d       = __floats2half2_rn(v.x, v.y);
        *(__half2*)(d + 2) = __floats2half2_rn(v.z, v.w);
    }
    __syncthreads();
    if (tid == 0) {
        float l0 = g2b[0], l1 = g2b[1];
        #pragma unroll
        for (int k = 0; k < 16; k++) {
            l0 += sh1[k] * g2w[k];
            l1 += sh1[k] * g2w[16 + k];
        }
        float m = fmaxf(l0, l1);
        float e0 = expf(l0 - m), e1 = expf(l1 - m);
        float inv = 1.f / (e0 + e1);
        s_gate[0] = e0 * inv;
        s_gate[1] = e1 * inv;
    }
    __syncthreads();
    float cw = s_gate[0], aw = s_gate[1];

    for (int pc = 0; pc < 8; pc++) {
        int p0 = p0base + pc * 128;
        __syncthreads();
        for (int i = tid; i < 4096; i += 256) {
            int c2 = i >> 7, j = i & 127;
            size_t off0 = ((size_t)(b * 64 + 2 * c2)) * HWN + p0 + j;
            size_t off1 = off0 + HWN;
            float v0 = cw * __half2float(g_convh[off0])
                     + aw * (__half2float(g_outh[off0]) + __half2float(g_outv[off0]));
            float v1 = cw * __half2float(g_convh[off1])
                     + aw * (__half2float(g_outh[off1]) + __half2float(g_outv[off1]));
            *(__half2*)(As + j * QH_ST + 2 * (c2 ^ SWZ(j))) = __floats2half2_rn(v0, v1);
        }
        __syncthreads();

        float acc[4][2][4];
        #pragma unroll
        for (int mt = 0; mt < 4; mt++)
            #pragma unroll
            for (int nt = 0; nt < 2; nt++)
                #pragma unroll
                for (int j = 0; j < 4; j++) acc[mt][nt][j] = 0.f;

        #pragma unroll
        for (int ks = 0; ks < 4; ks++) {
            int kh = ks * 16;
            int cw0 = ks * 8 + tq;
            uint32_t bf[2][2];
            #pragma unroll
            for (int nt = 0; nt < 2; nt++) {
                const __half* bpp = Ws + (nW + nt * 8 + gq) * QH_ST + kh + 2 * tq;
                bf[nt][0] = *(const uint32_t*)bpp;
                bf[nt][1] = *(const uint32_t*)(bpp + 8);
            }
            #pragma unroll
            for (int mt = 0; mt < 4; mt++) {
                int m = mW + mt * 16 + gq;
                int e0 = SWZ(m), e1 = SWZ(m + 8);
                const __half* r0 = As + m * QH_ST;
                const __half* r1 = As + (m + 8) * QH_ST;
                uint32_t af[4];
                af[0] = *(const uint32_t*)(r0 + 2 * (cw0 ^ e0));
                af[1] = *(const uint32_t*)(r1 + 2 * (cw0 ^ e1));
                af[2] = *(const uint32_t*)(r0 + 2 * ((cw0 + 4) ^ e0));
                af[3] = *(const uint32_t*)(r1 + 2 * ((cw0 + 4) ^ e1));
                #pragma unroll
                for (int nt = 0; nt < 2; nt++) MMA16(acc[mt][nt], af, bf[nt]);
            }
        }
        __syncthreads();

        #pragma unroll
        for (int mt = 0; mt < 4; mt++) {
            int m = mW + mt * 16 + gq;
            #pragma unroll
            for (int nt = 0; nt < 2; nt++) {
                int o = nW + nt * 8 + 2 * tq;
                S[o * 132 + m]           = acc[mt][nt][0];
                S[(o + 1) * 132 + m]     = acc[mt][nt][1];
                S[o * 132 + m + 8]       = acc[mt][nt][2];
                S[(o + 1) * 132 + m + 8] = acc[mt][nt][3];
            }
        }
        __syncthreads();
        for (int i = tid; i < 2048; i += 256) {
            int row = i >> 5, q = i & 31;
            float4 v = *(const float4*)(S + row * 132 + q * 4);
            float bb = __ldg(bp + row);
            v.x += bb; v.y += bb; v.z += bb; v.w += bb;
            *(float4*)(out + ((size_t)b * 64 + row) * HWN + p0 + q * 4) = v;
        }
    }
}

// ---------------- launcher ----------------
extern "C" void kernel_launch(void* const* d_in, const int* in_sizes, int n_in,
                              void* d_out, int out_size) {
    const float* x    = (const float*)d_in[0];
    const float* w3   = (const float*)d_in[1];
    const float* b3   = (const float*)d_in[2];
    const float* w5   = (const float*)d_in[3];
    const float* b5   = (const float*)d_in[4];
    const float* wqkv = (const float*)d_in[5];
    const float* scl  = (const float*)d_in[6];
    const float* g1w  = (const float*)d_in[7];
    const float* g1b  = (const float*)d_in[8];
    const float* g2w  = (const float*)d_in[9];
    const float* g2b  = (const float*)d_in[10];
    const float* wp   = (const float*)d_in[11];
    const float* bp   = (const float*)d_in[12];
    float* out = (float*)d_out;

    static bool configured = []() {
        cudaFuncSetAttribute(k_attn16, cudaFuncAttributeMaxDynamicSharedMemorySize, ATTN16_DYN);
        cudaFuncSetAttribute(k_qkv16, cudaFuncAttributeMaxDynamicSharedMemorySize, QKV16_DYN);
        cudaFuncSetAttribute(k_fuse16, cudaFuncAttributeMaxDynamicSharedMemorySize, QF16_DYN);
        return true;
    }();
    (void)configured;

    k_zero<<<1, 512>>>();
    k_conv_t<<<4096, 256>>>(x, w3, b3, w5, b5);
    k_qkv16<<<256, 256, QKV16_DYN>>>(x, wqkv);
    k_attn16<<<1024, 256, ATTN16_DYN>>>(scl);
    k_fuse16<<<256, 256, QF16_DYN>>>(wp, bp, g1w, g1b, g2w, g2b, out);
}

// round 15
// speedup vs baseline: 1.0751x; 1.0037x over previous
#include <cuda_runtime.h>
#include <cuda_fp16.h>
#include <math.h>
#include <stdint.h>

#define BSZ 4
#define DIM 64
#define HWN 65536          // 256*256

// ---------------- device scratch (static, allocation-free) ----------------
__device__ __align__(16) __half g_hA[BSZ * 192 * HWN];   // qkv fp16, [slice][x*256+y]
__device__ __align__(16) __half g_convh[BSZ * DIM * HWN];
__device__ __align__(16) __half g_outh[BSZ * DIM * HWN];
__device__ __align__(16) __half g_outv[BSZ * DIM * HWN];
__device__ float g_xsum[BSZ * DIM];
__device__ float g_sq  [2 * BSZ * DIM];     // [0..255]=sum q^2, [256..511]=sum k^2

// ============================ helpers ============================
#define MMA16(d, a, b) \
    asm volatile("mma.sync.aligned.m16n8k16.row.col.f32.f16.f16.f32 " \
        "{%0,%1,%2,%3},{%4,%5,%6,%7},{%8,%9},{%0,%1,%2,%3};" \
        : "+f"((d)[0]), "+f"((d)[1]), "+f"((d)[2]), "+f"((d)[3]) \
        : "r"((a)[0]), "r"((a)[1]), "r"((a)[2]), "r"((a)[3]), \
          "r"((b)[0]), "r"((b)[1]))

#define LDSM4T(R0, R1, R2, R3, a) \
    asm volatile("ldmatrix.sync.aligned.m8n8.x4.trans.shared.b16 {%0,%1,%2,%3}, [%4];" \
        : "=r"(R0), "=r"(R1), "=r"(R2), "=r"(R3) : "r"(a))

#define LDSM4(R0, R1, R2, R3, a) \
    asm volatile("ldmatrix.sync.aligned.m8n8.x4.shared.b16 {%0,%1,%2,%3}, [%4];" \
        : "=r"(R0), "=r"(R1), "=r"(R2), "=r"(R3) : "r"(a))

#define CPA16(dst_u32, src_ptr) \
    asm volatile("cp.async.ca.shared.global [%0], [%1], 16;" \
        :: "r"(dst_u32), "l"(src_ptr) : "memory")
#define CP_COMMIT() asm volatile("cp.async.commit_group;" ::: "memory")
#define CP_WAIT(n)  asm volatile("cp.async.wait_group %0;" :: "n"(n) : "memory")

__device__ __forceinline__ uint32_t h2u(__half2 h) {
    return *reinterpret_cast<uint32_t*>(&h);
}
#define SWZ(r) (((r) + ((r) >> 3)) & 3)

// ---------------- 0) zero accumulators ----------------
__global__ void k_zero() {
    int t = threadIdx.x;
    if (t < 256) g_xsum[t] = 0.f;
    g_sq[t] = 0.f; g_sq[t + 256] = 0.f;
}

// ---------------- 1) depthwise conv + channel-mean, 4 spatial tiles/block ----------------
__global__ void __launch_bounds__(256) k_conv_t(const float* __restrict__ x,
                       const float* __restrict__ w3, const float* __restrict__ b3,
                       const float* __restrict__ w5, const float* __restrict__ b5) {
    int bid = blockIdx.x;
    int bc = bid >> 4;
    int tbase = (bid & 15) * 4;
    int c = bc & 63;
    int tid = threadIdx.x;

    __shared__ float t[36 * 36];
    __shared__ float wc[25];
    __shared__ float sb[1];
    __shared__ float spart[8];
    if (tid < 25) {
        float w = w5[c * 25 + tid];
        int dh = tid / 5 - 2, dw = tid % 5 - 2;
        if (dh >= -1 && dh <= 1 && dw >= -1 && dw <= 1)
            w += w3[c * 9 + (dh + 1) * 3 + (dw + 1)];
        wc[tid] = w;
    }
    if (tid == 25) sb[0] = b3[c] + b5[c];

    const float* xp = x + (size_t)bc * HWN;
    int oh = tid >> 3, ow4 = (tid & 7) * 4;
    float xsum_t = 0.f;

    for (int tt = 0; tt < 4; tt++) {
        int tile = tbase + tt;
        int th = (tile >> 3) * 32, tw = (tile & 7) * 32;
        __syncthreads();
        for (int i = tid; i < 1296; i += 256) {
            int r = i / 36, col = i - r * 36;
            int gh = th - 2 + r, gw = tw - 2 + col;
            float v = 0.f;
            if ((unsigned)gh < 256u && (unsigned)gw < 256u) v = xp[gh * 256 + gw];
            t[i] = v;
        }
        __syncthreads();

        {
            const float* rp = t + (oh + 2) * 36 + ow4 + 2;
            xsum_t += rp[0] + rp[1] + rp[2] + rp[3];
        }
        float bias = sb[0];
        float a0 = bias, a1 = bias, a2 = bias, a3 = bias;
        #pragma unroll
        for (int dh = 0; dh < 5; dh++) {
            const float* row = t + (oh + dh) * 36 + ow4;
            float r0 = row[0], r1 = row[1], r2 = row[2], r3 = row[3];
            float r4 = row[4], r5 = row[5], r6 = row[6], r7 = row[7];
            const float* w = wc + dh * 5;
            float w0 = w[0], w1 = w[1], w2 = w[2], w3v = w[3], w4 = w[4];
            a0 += r0 * w0 + r1 * w1 + r2 * w2 + r3 * w3v + r4 * w4;
            a1 += r1 * w0 + r2 * w1 + r3 * w2 + r4 * w3v + r5 * w4;
            a2 += r2 * w0 + r3 * w1 + r4 * w2 + r5 * w3v + r6 * w4;
            a3 += r3 * w0 + r4 * w1 + r5 * w2 + r6 * w3v + r7 * w4;
        }
        uint2 u;
        u.x = h2u(__floats2half2_rn(a0, a1));
        u.y = h2u(__floats2half2_rn(a2, a3));
        *(uint2*)(g_convh + (size_t)bc * HWN + (th + oh) * 256 + tw + ow4) = u;
    }

    #pragma unroll
    for (int off = 16; off; off >>= 1) xsum_t += __shfl_xor_sync(0xFFFFFFFFu, xsum_t, off);
    if ((tid & 31) == 0) spart[tid >> 5] = xsum_t;
    __syncthreads();
    if (tid == 0) {
        float xs = 0.f;
        #pragma unroll
        for (int k = 0; k < 8; k++) xs += spart[k];
        atomicAdd(&g_xsum[bc], xs);
    }
}

// ---------------- 2) QKV projection: fp16 m16n8k16, 8 pixel-chunks/block ----------------
#define QH_ST 72
#define QKV16_DYN 96768

__global__ void __launch_bounds__(256, 2) k_qkv16(const float* __restrict__ x,
                                                  const float* __restrict__ wqkv) {
    extern __shared__ char qsm[];
    __half* As = (__half*)qsm;
    __half* Ws = (__half*)(qsm + 18432);
    float*  S  = (float*)(qsm + 46080);

    int tid = threadIdx.x;
    int wid = tid >> 5, lane = tid & 31;
    int gq = lane >> 2, tq = lane & 3;
    int wm = wid & 1, wn = wid >> 1;
    int mW = wm * 64, nW = wn * 48;

    int bid = blockIdx.x;
    int b = bid >> 6;
    int p0base = (bid & 63) << 10;
    const float* xb = x + (size_t)b * 64 * HWN;

    for (int i = tid; i < 192 * 16; i += 256) {
        int o = i >> 4, c4 = i & 15;
        float4 v = *(const float4*)(wqkv + o * 64 + c4 * 4);
        __half* d = Ws + o * QH_ST + c4 * 4;
        *(__half2*)d       = __floats2half2_rn(v.x, v.y);
        *(__half2*)(d + 2) = __floats2half2_rn(v.z, v.w);
    }

    for (int pc = 0; pc < 8; pc++) {
        int p0 = p0base + pc * 128;
        __syncthreads();
        for (int i = tid; i < 4096; i += 256) {
            int c2 = i >> 7, j = i & 127;
            float v0 = xb[(size_t)(2 * c2) * HWN + p0 + j];
            float v1 = xb[(size_t)(2 * c2 + 1) * HWN + p0 + j];
            *(__half2*)(As + j * QH_ST + 2 * (c2 ^ SWZ(j))) = __floats2half2_rn(v0, v1);
        }
        __syncthreads();

        float acc[4][6][4];
        #pragma unroll
        for (int mt = 0; mt < 4; mt++)
            #pragma unroll
            for (int nt = 0; nt < 6; nt++)
                #pragma unroll
                for (int j = 0; j < 4; j++) acc[mt][nt][j] = 0.f;

        #pragma unroll
        for (int ks = 0; ks < 4; ks++) {
            int kh = ks * 16;
            int cw0 = ks * 8 + tq;
            uint32_t bf[6][2];
            #pragma unroll
            for (int nt = 0; nt < 6; nt++) {
                const __half* bp = Ws + (nW + nt * 8 + gq) * QH_ST + kh + 2 * tq;
                bf[nt][0] = *(const uint32_t*)bp;
                bf[nt][1] = *(const uint32_t*)(bp + 8);
            }
            #pragma unroll
            for (int mt = 0; mt < 4; mt++) {
                int m = mW + mt * 16 + gq;
                int e0 = SWZ(m), e1 = SWZ(m + 8);
                const __half* r0 = As + m * QH_ST;
                const __half* r1 = As + (m + 8) * QH_ST;
                uint32_t af[4];
                af[0] = *(const uint32_t*)(r0 + 2 * (cw0 ^ e0));
                af[1] = *(const uint32_t*)(r1 + 2 * (cw0 ^ e1));
                af[2] = *(const uint32_t*)(r0 + 2 * ((cw0 + 4) ^ e0));
                af[3] = *(const uint32_t*)(r1 + 2 * ((cw0 + 4) ^ e1));
                #pragma unroll
                for (int nt = 0; nt < 6; nt++) MMA16(acc[mt][nt], af, bf[nt]);
            }
        }
        __syncthreads();

        __half* outb = g_hA + (size_t)b * 192 * HWN + p0;
        #pragma unroll
        for (int pass = 0; pass < 2; pass++) {
            if ((wn >> 1) == pass) {
                int ob = nW - pass * 96;
                #pragma unroll
                for (int mt = 0; mt < 4; mt++) {
                    int m = mW + mt * 16 + gq;
                    #pragma unroll
                    for (int nt = 0; nt < 6; nt++) {
                        int ol = ob + nt * 8 + 2 * tq;
                        S[ol * 132 + m]           = acc[mt][nt][0];
                        S[(ol + 1) * 132 + m]     = acc[mt][nt][1];
                        S[ol * 132 + m + 8]       = acc[mt][nt][2];
                        S[(ol + 1) * 132 + m + 8] = acc[mt][nt][3];
                    }
                }
            }
            __syncthreads();
            for (int i = tid; i < 96 * 32; i += 256) {
                int row = i >> 5, q = i & 31;
                float4 v = *(const float4*)(S + row * 132 + q * 4);
                int o = pass * 96 + row;
                uint2 u;
                u.x = h2u(__floats2half2_rn(v.x, v.y));
                u.y = h2u(__floats2half2_rn(v.z, v.w));
                *(uint2*)(outb + (size_t)o * HWN + q * 4) = u;
                if (o < 128) {
                    float sq = v.x * v.x + v.y * v.y + v.z * v.z + v.w * v.w;
                    #pragma unroll
                    for (int off = 16; off; off >>= 1) sq += __shfl_xor_sync(0xFFFFFFFFu, sq, off);
                    if ((tid & 31) == 0)
                        atomicAdd(&g_sq[o < 64 ? b * 64 + o : 256 + b * 64 + o - 64], sq);
                }
            }
            __syncthreads();
        }
    }
}

// ---------------- 3) fp16 mma attention, all-ldmatrix fragment loads ----------------
#define H_AS(bi) ((bi) * 9216)
#define H_BS(bi) (18432 + (bi) * 18432)
#define H_PS 55296
#define AT_ST 136
#define BT_ST 264
#define P_ST 296
#define ATTN16_DYN ((55296 + 128 * 296) * 2)   // 186368 bytes

__global__ void __launch_bounds__(256, 1) k_attn16(const float* __restrict__ scale) {
    extern __shared__ char dynsm[];
    __half* Hs = (__half*)dynsm;
    __half* Ps = Hs + H_PS;
    float*  Sf = (float*)dynsm;
    __shared__ float s_rows[512];
    __shared__ float s_inv[128];

    uint32_t smb = (uint32_t)__cvta_generic_to_shared(dynsm);
    uint32_t psb = smb + H_PS * 2;

    int tid = threadIdx.x;
    int wid = tid >> 5, lane = tid & 31;
    int gq = lane >> 2, tq = lane & 3;
    int jj = lane & 7, lg = lane >> 3;
    int wm = wid & 1, wn = wid >> 1;
    int mW = wm * 64, nW = wn * 64;

    int bid = blockIdx.x;
    int s = bid & 255, half = (bid >> 8) & 1, dir = bid >> 9;
    int b = s >> 6, ch = s & 63, hd = ch & 7;
    int m0 = half << 7;

    size_t sbase = ((size_t)b * 192 + ch) * HWN;
    const __half* Qp = g_hA + sbase;
    const __half* Kp = Qp + (size_t)64 * HWN;
    const __half* Vp = Qp + (size_t)128 * HWN;

    float nq = fmaxf(sqrtf(g_sq[s]), 1e-12f);
    float nk = fmaxf(sqrtf(g_sq[256 + s]), 1e-12f);
    float alpha = scale[hd] / (nq * nk);

    float acc[4][8][4];
    #pragma unroll
    for (int mt = 0; mt < 4; mt++)
        #pragma unroll
        for (int nt = 0; nt < 8; nt++)
            #pragma unroll
            for (int j = 0; j < 4; j++) acc[mt][nt][j] = 0.f;

    #define LOAD_A_DIR(bi, c0) do { \
        for (int i = tid; i < 1024; i += 256) { \
            int r = i >> 3, q = i & 7; \
            CPA16(smb + (H_AS(bi) + r * QH_ST + q * 8) * 2, \
                  Qp + (size_t)(m0 + r) * 256 + (c0) + q * 8); \
        } } while (0)
    #define LOAD_A_TRN(bi, c0) do { \
        for (int i = tid; i < 1024; i += 256) { \
            int r = i >> 4, q = i & 15; \
            CPA16(smb + (H_AS(bi) + r * AT_ST + q * 8) * 2, \
                  Qp + (size_t)((c0) + r) * 256 + m0 + q * 8); \
        } } while (0)
    #define LOAD_B_DIR(Bp, bi, c0) do { \
        for (int i = tid; i < 2048; i += 256) { \
            int r = i >> 3, q = i & 7; \
            CPA16(smb + (H_BS(bi) + r * QH_ST + q * 8) * 2, \
                  (Bp) + (size_t)r * 256 + (c0) + q * 8); \
        } } while (0)
    #define LOAD_B_TRN(Bp, bi, c0) do { \
        for (int i = tid; i < 2048; i += 256) { \
            int r = i >> 5, q = i & 31; \
            CPA16(smb + (H_BS(bi) + r * BT_ST + q * 8) * 2, \
                  (Bp) + (size_t)((c0) + r) * 256 + q * 8); \
        } } while (0)
    #define LOAD_G1(bi, c0) do { \
        if (dir == 0) { LOAD_A_DIR(bi, c0); LOAD_B_DIR(Kp, bi, c0); } \
        else          { LOAD_A_TRN(bi, c0); LOAD_B_TRN(Kp, bi, c0); } } while (0)

    // ldmatrix per-lane offsets (in halves)
    int atrn_off = (jj + ((lg & 2) ? 8 : 0)) * AT_ST + (lg & 1) * 8;          // trans A
    int btrn_off = (jj + ((lg & 1) ? 8 : 0)) * BT_ST + ((lg & 2) ? 8 : 0);    // trans B
    int adir_off = ((lg & 1) * 8 + jj) * QH_ST + ((lg & 2) ? 8 : 0);          // direct A
    int bdir_off = (jj + ((lg & 2) ? 8 : 0)) * QH_ST + ((lg & 1) ? 8 : 0);    // direct B
    int pdir_off = ((lg & 1) * 8 + jj) * P_ST + ((lg & 2) ? 8 : 0);           // P (direct A)

    LOAD_G1(0, 0);
    CP_COMMIT();

    // ======================= GEMM1 =======================
    for (int cc = 0; cc < 4; cc++) {
        if (cc < 3) {
            LOAD_G1((cc + 1) & 1, (cc + 1) * 64);
            CP_COMMIT();
            CP_WAIT(1);
        } else {
            CP_WAIT(0);
        }
        __syncthreads();
        int cb = cc & 1;
        if (dir == 0) {
            uint32_t abase = smb + (H_AS(cb) + adir_off + mW * QH_ST) * 2;
            uint32_t bbase = smb + (H_BS(cb) + bdir_off + nW * QH_ST) * 2;
            #pragma unroll
            for (int ks = 0; ks < 4; ks++) {
                int k0 = ks * 16;
                uint32_t bf[8][2];
                #pragma unroll
                for (int p = 0; p < 4; p++) {
                    LDSM4(bf[2 * p][0], bf[2 * p][1], bf[2 * p + 1][0], bf[2 * p + 1][1],
                          bbase + (p * 16 * QH_ST + k0) * 2);
                }
                #pragma unroll
                for (int mt = 0; mt < 4; mt++) {
                    uint32_t af[4];
                    LDSM4(af[0], af[1], af[2], af[3],
                          abase + (mt * 16 * QH_ST + k0) * 2);
                    #pragma unroll
                    for (int nt = 0; nt < 8; nt++) MMA16(acc[mt][nt], af, bf[nt]);
                }
            }
        } else {
            uint32_t abase = smb + (H_AS(cb) + atrn_off + mW) * 2;
            uint32_t bbase = smb + (H_BS(cb) + btrn_off + nW) * 2;
            #pragma unroll
            for (int ks = 0; ks < 4; ks++) {
                int k0 = ks * 16;
                uint32_t bf[8][2];
                #pragma unroll
                for (int p = 0; p < 4; p++) {
                    LDSM4T(bf[2 * p][0], bf[2 * p][1], bf[2 * p + 1][0], bf[2 * p + 1][1],
                           bbase + (k0 * BT_ST + p * 16) * 2);
                }
                #pragma unroll
                for (int mt = 0; mt < 4; mt++) {
                    uint32_t af[4];
                    LDSM4T(af[0], af[1], af[2], af[3],
                           abase + (k0 * AT_ST + mt * 16) * 2);
                    #pragma unroll
                    for (int nt = 0; nt < 8; nt++) MMA16(acc[mt][nt], af, bf[nt]);
                }
            }
        }
        __syncthreads();
    }

    if (dir == 0) { LOAD_B_TRN(Vp, 0, 0); } else { LOAD_B_DIR(Vp, 0, 0); }
    CP_COMMIT();
    if (dir == 0) { LOAD_B_TRN(Vp, 1, 64); } else { LOAD_B_DIR(Vp, 1, 64); }
    CP_COMMIT();

    // ======================= softmax =======================
    #pragma unroll
    for (int mt = 0; mt < 4; mt++) {
        int r0 = mW + mt * 16 + gq;
        float rs0 = 0.f, rs1 = 0.f;
        #pragma unroll
        for (int nt = 0; nt < 8; nt++) {
            float e0 = __expf(fminf(acc[mt][nt][0] * alpha, 80.f));
            float e1 = __expf(fminf(acc[mt][nt][1] * alpha, 80.f));
            float e2 = __expf(fminf(acc[mt][nt][2] * alpha, 80.f));
            float e3 = __expf(fminf(acc[mt][nt][3] * alpha, 80.f));
            __half2 h01 = __floats2half2_rn(e0, e1);
            __half2 h23 = __floats2half2_rn(e2, e3);
            float2 f01 = __half22float2(h01);
            float2 f23 = __half22float2(h23);
            rs0 += f01.x + f01.y;
            rs1 += f23.x + f23.y;
            int c = nW + nt * 8 + 2 * tq;
            *(__half2*)(Ps + r0 * P_ST + c)       = h01;
            *(__half2*)(Ps + (r0 + 8) * P_ST + c) = h23;
        }
        rs0 += __shfl_xor_sync(0xFFFFFFFFu, rs0, 1);
        rs0 += __shfl_xor_sync(0xFFFFFFFFu, rs0, 2);
        rs1 += __shfl_xor_sync(0xFFFFFFFFu, rs1, 1);
        rs1 += __shfl_xor_sync(0xFFFFFFFFu, rs1, 2);
        if (tq == 0) {
            s_rows[wn * 128 + r0]     = rs0;
            s_rows[wn * 128 + r0 + 8] = rs1;
        }
    }
    __syncthreads();
    if (tid < 128)
        s_inv[tid] = 1.0f / (s_rows[tid] + s_rows[128 + tid] + s_rows[256 + tid] + s_rows[384 + tid]);

    #pragma unroll
    for (int mt = 0; mt < 4; mt++)
        #pragma unroll
        for (int nt = 0; nt < 8; nt++)
            #pragma unroll
            for (int j = 0; j < 4; j++) acc[mt][nt][j] = 0.f;

    // ======================= GEMM2 (prefetch depth 2) =======================
    for (int cc = 0; cc < 4; cc++) {
        if (cc < 3) CP_WAIT(1); else CP_WAIT(0);
        __syncthreads();
        int cb = cc & 1;
        uint32_t bbase_t = smb + (H_BS(cb) + btrn_off + nW) * 2;
        uint32_t bbase_d = smb + (H_BS(cb) + bdir_off + nW * QH_ST) * 2;
        uint32_t pbase   = psb + (pdir_off + mW * P_ST + cc * 64) * 2;
        #pragma unroll
        for (int ks = 0; ks < 4; ks++) {
            int k0 = ks * 16;
            uint32_t bf[8][2];
            if (dir == 0) {
                #pragma unroll
                for (int p = 0; p < 4; p++) {
                    LDSM4T(bf[2 * p][0], bf[2 * p][1], bf[2 * p + 1][0], bf[2 * p + 1][1],
                           bbase_t + (k0 * BT_ST + p * 16) * 2);
                }
            } else {
                #pragma unroll
                for (int p = 0; p < 4; p++) {
                    LDSM4(bf[2 * p][0], bf[2 * p][1], bf[2 * p + 1][0], bf[2 * p + 1][1],
                          bbase_d + (p * 16 * QH_ST + k0) * 2);
                }
            }
            #pragma unroll
            for (int mt = 0; mt < 4; mt++) {
                uint32_t af[4];
                LDSM4(af[0], af[1], af[2], af[3],
                      pbase + (mt * 16 * P_ST + k0) * 2);
                #pragma unroll
                for (int nt = 0; nt < 8; nt++) MMA16(acc[mt][nt], af, bf[nt]);
            }
        }
        __syncthreads();
        if (cc < 2) {
            if (dir == 0) { LOAD_B_TRN(Vp, cc & 1, (cc + 2) * 64); }
            else          { LOAD_B_DIR(Vp, cc & 1, (cc + 2) * 64); }
            CP_COMMIT();
        }
    }

    // ======================= epilogue: single-pass staging =======================
    if (dir == 0) {
        #pragma unroll
        for (int mt = 0; mt < 4; mt++) {
            int rg = mW + mt * 16 + gq;
            float i0 = s_inv[rg], i1 = s_inv[rg + 8];
            #pragma unroll
            for (int nt = 0; nt < 8; nt++) {
                int c = nW + nt * 8 + 2 * tq;
                *(float2*)(Sf + rg * 260 + c) =
                    make_float2(acc[mt][nt][0] * i0, acc[mt][nt][1] * i0);
                *(float2*)(Sf + (rg + 8) * 260 + c) =
                    make_float2(acc[mt][nt][2] * i1, acc[mt][nt][3] * i1);
            }
        }
        __syncthreads();
        __half* O = g_outh + (size_t)s * HWN;
        for (int i = tid; i < 8192; i += 256) {
            int r = i >> 6, q = i & 63;
            float4 u = *(const float4*)(Sf + r * 260 + q * 4);
            uint2 o;
            o.x = h2u(__floats2half2_rn(u.x, u.y));
            o.y = h2u(__floats2half2_rn(u.z, u.w));
            *(uint2*)(O + (size_t)(m0 + r) * 256 + q * 4) = o;
        }
    } else {
        #pragma unroll
        for (int mt = 0; mt < 4; mt++) {
            int rg = mW + mt * 16 + gq;
            float i0 = s_inv[rg], i1 = s_inv[rg + 8];
            #pragma unroll
            for (int nt = 0; nt < 8; nt++) {
                int c = nW + nt * 8 + 2 * tq;
                Sf[c * 132 + rg]           = acc[mt][nt][0] * i0;
                Sf[(c + 1) * 132 + rg]     = acc[mt][nt][1] * i0;
                Sf[c * 132 + rg + 8]       = acc[mt][nt][2] * i1;
                Sf[(c + 1) * 132 + rg + 8] = acc[mt][nt][3] * i1;
            }
        }
        __syncthreads();
        __half* O = g_outv + (size_t)s * HWN;
        for (int i = tid; i < 8192; i += 256) {
            int n = i >> 5, q = i & 31;
            float4 u = *(const float4*)(Sf + n * 132 + q * 4);
            uint2 o;
            o.x = h2u(__floats2half2_rn(u.x, u.y));
            o.y = h2u(__floats2half2_rn(u.z, u.w));
            *(uint2*)(O + (size_t)n * 256 + m0 + q * 4) = o;
        }
    }
    #undef LOAD_A_DIR
    #undef LOAD_A_TRN
    #undef LOAD_B_DIR
    #undef LOAD_B_TRN
    #undef LOAD_G1
}

// ---------------- 4) gated fusion + projection (gate MLP fused in) ----------------
#define QF16_DYN 61440

__global__ void __launch_bounds__(256, 2) k_fuse16(const float* __restrict__ wp,
                                                   const float* __restrict__ bp,
                                                   const float* __restrict__ g1w,
                                                   const float* __restrict__ g1b,
                                                   const float* __restrict__ g2w,
                                                   const float* __restrict__ g2b,
                                                   float* __restrict__ out) {
    extern __shared__ char fsm[];
    __half* As = (__half*)fsm;
    __half* Ws = (__half*)(fsm + 18432);
    float*  S  = (float*)(fsm + 27648);
    __shared__ float sh1[16];
    __shared__ float s_gate[2];

    int tid = threadIdx.x;
    int wid = tid >> 5, lane = tid & 31;
    int gq = lane >> 2, tq = lane & 3;
    int wm = wid & 1, wn = wid >> 1;
    int mW = wm * 64, nW = wn * 16;

    int bid = blockIdx.x;
    int b = bid >> 6;
    int p0base = (bid & 63) << 10;

    if (tid < 16) {
        float a = g1b[tid];
        #pragma unroll
        for (int c = 0; c < 64; c++)
            a += (g_xsum[b * 64 + c] * (1.0f / HWN)) * g1w[tid * 64 + c];
        sh1[tid] = fmaxf(a, 0.f);
    }
    for (int i = tid; i < 64 * 16; i += 256) {
        int o = i >> 4, c4 = i & 15;
        float4 v = *(const float4*)(wp + o * 64 + c4 * 4);
        __half* d = Ws + o * QH_ST + c4 * 4;
        *(__half2*)d       = __floats2half2_rn(v.x, v.y);
        *(__half2*)(d + 2) = __floats2half2_rn(v.z, v.w);
    }
    __syncthreads();
    if (tid == 0) {
        float l0 = g2b[0], l1 = g2b[1];
        #pragma unroll
        for (int k = 0; k < 16; k++) {
            l0 += sh1[k] * g2w[k];
            l1 += sh1[k] * g2w[16 + k];
        }
        float m = fmaxf(l0, l1);
        float e0 = expf(l0 - m), e1 = expf(l1 - m);
        float inv = 1.f / (e0 + e1);
        s_gate[0] = e0 * inv;
        s_gate[1] = e1 * inv;
    }
    __syncthreads();
    float cw = s_gate[0], aw = s_gate[1];

    for (int pc = 0; pc < 8; pc++) {
        int p0 = p0base + pc * 128;
        __syncthreads();
        for (int i = tid; i < 4096; i += 256) {
            int c2 = i >> 7, j = i & 127;
            size_t off0 = ((size_t)(b * 64 + 2 * c2)) * HWN + p0 + j;
            size_t off1 = off0 + HWN;
            float v0 = cw * __half2float(g_convh[off0])
                     + aw * (__half2float(g_outh[off0]) + __half2float(g_outv[off0]));
            float v1 = cw * __half2float(g_convh[off1])
                     + aw * (__half2float(g_outh[off1]) + __half2float(g_outv[off1]));
            *(__half2*)(As + j * QH_ST + 2 * (c2 ^ SWZ(j))) = __floats2half2_rn(v0, v1);
        }
        __syncthreads();

        float acc[4][2][4];
        #pragma unroll
        for (int mt = 0; mt < 4; mt++)
            #pragma unroll
            for (int nt = 0; nt < 2; nt++)
                #pragma unroll
                for (int j = 0; j < 4; j++) acc[mt][nt][j] = 0.f;

        #pragma unroll
        for (int ks = 0; ks < 4; ks++) {
            int kh = ks * 16;
            int cw0 = ks * 8 + tq;
            uint32_t bf[2][2];
            #pragma unroll
            for (int nt = 0; nt < 2; nt++) {
                const __half* bpp = Ws + (nW + nt * 8 + gq) * QH_ST + kh + 2 * tq;
                bf[nt][0] = *(const uint32_t*)bpp;
                bf[nt][1] = *(const uint32_t*)(bpp + 8);
            }
            #pragma unroll
            for (int mt = 0; mt < 4; mt++) {
                int m = mW + mt * 16 + gq;
                int e0 = SWZ(m), e1 = SWZ(m + 8);
                const __half* r0 = As + m * QH_ST;
                const __half* r1 = As + (m + 8) * QH_ST;
                uint32_t af[4];
                af[0] = *(const uint32_t*)(r0 + 2 * (cw0 ^ e0));
                af[1] = *(const uint32_t*)(r1 + 2 * (cw0 ^ e1));
                af[2] = *(const uint32_t*)(r0 + 2 * ((cw0 + 4) ^ e0));
                af[3] = *(const uint32_t*)(r1 + 2 * ((cw0 + 4) ^ e1));
                #pragma unroll
                for (int nt = 0; nt < 2; nt++) MMA16(acc[mt][nt], af, bf[nt]);
            }
        }
        __syncthreads();

        #pragma unroll
        for (int mt = 0; mt < 4; mt++) {
            int m = mW + mt * 16 + gq;
            #pragma unroll
            for (int nt = 0; nt < 2; nt++) {
                int o = nW + nt * 8 + 2 * tq;
                S[o * 132 + m]           = acc[mt][nt][0];
                S[(o + 1) * 132 + m]     = acc[mt][nt][1];
                S[o * 132 + m + 8]       = acc[mt][nt][2];
                S[(o + 1) * 132 + m + 8] = acc[mt][nt][3];
            }
        }
        __syncthreads();
        for (int i = tid; i < 2048; i += 256) {
            int row = i >> 5, q = i & 31;
            float4 v = *(const float4*)(S + row * 132 + q * 4);
            float bb = __ldg(bp + row);
            v.x += bb; v.y += bb; v.z += bb; v.w += bb;
            *(float4*)(out + ((size_t)b * 64 + row) * HWN + p0 + q * 4) = v;
        }
    }
}

// ---------------- launcher ----------------
extern "C" void kernel_launch(void* const* d_in, const int* in_sizes, int n_in,
                              void* d_out, int out_size) {
    const float* x    = (const float*)d_in[0];
    const float* w3   = (const float*)d_in[1];
    const float* b3   = (const float*)d_in[2];
    const float* w5   = (const float*)d_in[3];
    const float* b5   = (const float*)d_in[4];
    const float* wqkv = (const float*)d_in[5];
    const float* scl  = (const float*)d_in[6];
    const float* g1w  = (const float*)d_in[7];
    const float* g1b  = (const float*)d_in[8];
    const float* g2w  = (const float*)d_in[9];
    const float* g2b  = (const float*)d_in[10];
    const float* wp   = (const float*)d_in[11];
    const float* bp   = (const float*)d_in[12];
    float* out = (float*)d_out;

    static bool configured = []() {
        cudaFuncSetAttribute(k_attn16, cudaFuncAttributeMaxDynamicSharedMemorySize, ATTN16_DYN);
        cudaFuncSetAttribute(k_qkv16, cudaFuncAttributeMaxDynamicSharedMemorySize, QKV16_DYN);
        cudaFuncSetAttribute(k_fuse16, cudaFuncAttributeMaxDynamicSharedMemorySize, QF16_DYN);
        return true;
    }();
    (void)configured;

    k_zero<<<1, 512>>>();
    k_conv_t<<<4096, 256>>>(x, w3, b3, w5, b5);
    k_qkv16<<<256, 256, QKV16_DYN>>>(x, wqkv);
    k_attn16<<<1024, 256, ATTN16_DYN>>>(scl);
    k_fuse16<<<256, 256, QF16_DYN>>>(wp, bp, g1w, g1b, g2w, g2b, out);
}